// round 5
// baseline (speedup 1.0000x reference)
#include <cuda_runtime.h>
#include <stdint.h>

// Key space: b in [0,256), px,py,pz in [0,128)  ->  2^29 keys -> 2^24 32-bit words
#define NWORDS    (1u << 24)
#define TPB       256
#define WPT       16                      // words per thread in the sweep
#define BLK_WORDS (TPB * WPT)             // 4096 words per block
#define NBLK      (NWORDS / BLK_WORDS)    // 4096 blocks
#define NSEG      (NWORDS / 8)            // 8-word (32B sector) segments
#define MAXN      4194304u

#define FLAG_AGG  (1u << 30)
#define FLAG_PRE  (2u << 30)
#define VAL_MASK  0x3FFFFFFFu

__device__ uint32_t g_bitmap[NWORDS];     // 64 MB presence bitmap
__device__ uint32_t g_segBase[NSEG];      //  8 MB absolute rank at each 8-word segment
__device__ uint32_t g_keys[MAXN];         // 16 MB packed (pos<<29)|key per point
__device__ uint32_t g_status[NBLK];       // decoupled-lookback status (flag|value)

// ---------------------------------------------------------------- K0: init
__global__ __launch_bounds__(TPB) void k0_init(float* __restrict__ outF, uint32_t n)
{
    uint32_t i = blockIdx.x * TPB + threadIdx.x;
    uint32_t bm4 = NWORDS / 4;                    // 4M uint4 for bitmap
    uint32_t ft4 = n / 4;                         // 1M float4 for feats
    if (i < bm4) {
        ((uint4*)g_bitmap)[i] = make_uint4(0u, 0u, 0u, 0u);
    } else if (i < bm4 + ft4) {
        ((float4*)outF)[i - bm4] = make_float4(0.f, 0.f, 0.f, 0.f);
    } else if (i < bm4 + ft4 + NBLK) {
        g_status[i - (bm4 + ft4)] = 0u;
    }
}

// ---------------------------------------------------------------- K1: mark + pack
__global__ __launch_bounds__(TPB) void k1_build(const int4* __restrict__ coords, int n)
{
    int i = blockIdx.x * TPB + threadIdx.x;
    if (i >= n) return;
    int4 c = coords[i];
    uint32_t key = ((uint32_t)c.x << 21) | ((uint32_t)(c.y >> 1) << 14)
                 | ((uint32_t)(c.z >> 1) << 7) | (uint32_t)(c.w >> 1);
    uint32_t pos = (uint32_t)((c.y & 1) | ((c.z & 1) << 1) | ((c.w & 1) << 2));
    g_keys[i] = (pos << 29) | key;
    atomicOr(&g_bitmap[key >> 5], 1u << (key & 31));
}

// ---------------------------------------------------------------- K2: fused sweep
// Single bitmap pass: popcount + block scan (warp shuffles), decoupled lookback,
// then emit sorted out_coords + per-segment rank bases.
__global__ __launch_bounds__(TPB) void k2_sweep(float* __restrict__ out)
{
    __shared__ uint32_t s_warp[TPB / 32];
    __shared__ uint32_t s_excl;
    uint32_t t    = threadIdx.x;
    uint32_t lane = t & 31, wid = t >> 5;
    uint32_t bid  = blockIdx.x;
    uint32_t base = bid * BLK_WORDS + t * WPT;

    uint32_t words[WPT];
    const uint4* p = (const uint4*)(g_bitmap + base);
    uint32_t tot = 0;
#pragma unroll
    for (int i = 0; i < 4; i++) {
        uint4 v = p[i];
        words[4 * i + 0] = v.x; words[4 * i + 1] = v.y;
        words[4 * i + 2] = v.z; words[4 * i + 3] = v.w;
    }
#pragma unroll
    for (int i = 0; i < WPT; i++) tot += __popc(words[i]);

    // warp-level inclusive scan
    uint32_t inc = tot;
#pragma unroll
    for (int o = 1; o < 32; o <<= 1) {
        uint32_t x = __shfl_up_sync(0xFFFFFFFFu, inc, o);
        if (lane >= o) inc += x;
    }
    if (lane == 31) s_warp[wid] = inc;
    __syncthreads();
    // warp 0 scans the 8 warp sums
    if (wid == 0) {
        uint32_t v = (lane < TPB / 32) ? s_warp[lane] : 0u;
        uint32_t vi = v;
#pragma unroll
        for (int o = 1; o < TPB / 32; o <<= 1) {
            uint32_t x = __shfl_up_sync(0xFFFFFFFFu, vi, o);
            if (lane >= o) vi += x;
        }
        if (lane < TPB / 32) s_warp[lane] = vi - v;   // exclusive warp prefix
        // publish aggregate ASAP
        if (lane == TPB / 32 - 1) {
            uint32_t blockAgg = vi;
            if (bid == 0) {
                atomicExch(&g_status[0], FLAG_PRE | blockAgg);
                s_excl = 0u;
            } else {
                atomicExch(&g_status[bid], FLAG_AGG | blockAgg);
            }
            s_warp[TPB / 32 - 1] = vi - v;            // keep prefix consistent
        }
    }
    __syncthreads();
    uint32_t threadExcl = s_warp[wid] + inc - tot;    // block-wide exclusive prefix
    uint32_t blockAgg;
    {
        // recover aggregate: last warp prefix + its total (broadcast via shared)
        blockAgg = 0;  // only needed by lookback warp; recompute there
    }

    // warp 0: decoupled lookback
    if (bid != 0 && wid == 0) {
        uint32_t excl = 0;
        int pos = (int)bid - 1;
        while (pos >= 0) {
            int idx = pos - (int)lane;
            uint32_t sv;
            if (idx >= 0) {
                do { sv = *((volatile uint32_t*)&g_status[idx]); }
                while ((sv >> 30) == 0u);
            } else {
                sv = FLAG_PRE;
            }
            uint32_t flag = sv >> 30;
            uint32_t val  = sv & VAL_MASK;
            uint32_t ball = __ballot_sync(0xFFFFFFFFu, flag == 2u);
            if (ball) {
                int fp = __ffs(ball) - 1;
                uint32_t contrib = ((int)lane <= fp) ? val : 0u;
                excl += __reduce_add_sync(0xFFFFFFFFu, contrib);
                break;
            } else {
                excl += __reduce_add_sync(0xFFFFFFFFu, val);
                pos -= 32;
            }
        }
        if (lane == 0) s_excl = excl;
    }
    __syncthreads();
    if (bid != 0 && t == TPB - 1) {
        // this thread knows block total = threadExcl + tot
        atomicExch(&g_status[bid], FLAG_PRE | ((s_excl + threadExcl + tot) & VAL_MASK));
    }

    // emit coords (sorted) + segment rank bases
    uint32_t running = s_excl + threadExcl;
    float4* outc = (float4*)out;
#pragma unroll
    for (int i = 0; i < WPT; i++) {
        uint32_t w = base + i;
        if ((i & 7) == 0) g_segBase[w >> 3] = running;
        uint32_t word = words[i];
        while (word) {
            int b = __ffs(word) - 1;
            word &= word - 1;
            uint32_t key = (w << 5) + (uint32_t)b;
            outc[running++] = make_float4((float)(key >> 21),
                                          (float)((key >> 14) & 127),
                                          (float)((key >> 7) & 127),
                                          (float)(key & 127));
        }
    }
}

// ---------------------------------------------------------------- K3: tail fill
__global__ __launch_bounds__(TPB) void k3_tail(float* __restrict__ out, int n)
{
    uint32_t total = g_status[NBLK - 1] & VAL_MASK;
    float4* outc = (float4*)out;
    for (uint32_t i = total + blockIdx.x * blockDim.x + threadIdx.x;
         i < (uint32_t)n; i += gridDim.x * blockDim.x)
        outc[i] = make_float4(-1.f, -1.f, -1.f, -1.f);
}

// ---------------------------------------------------------------- K4: scatter feats
__global__ __launch_bounds__(TPB) void k4_feats(const float* __restrict__ kern,
                                                float* __restrict__ outF, int n)
{
    int i = blockIdx.x * TPB + threadIdx.x;
    if (i >= n) return;
    uint32_t packed = g_keys[i];
    uint32_t pos = packed >> 29;
    uint32_t key = packed & ((1u << 29) - 1u);
    uint32_t w = key >> 5, bit = key & 31;
    uint32_t seg = w >> 3, j = w & 7;

    const uint4* sp = (const uint4*)(g_bitmap + (seg << 3));
    uint4 lo = sp[0], hi = sp[1];
    uint32_t sw[8] = { lo.x, lo.y, lo.z, lo.w, hi.x, hi.y, hi.z, hi.w };

    uint32_t rank = g_segBase[seg];
#pragma unroll
    for (uint32_t k = 0; k < 8; k++)
        if (k < j) rank += __popc(sw[k]);
    rank += __popc(sw[j] & ((1u << bit) - 1u));

    float contrib = (float)(1u << pos) * __ldg(&kern[pos]);
    atomicAdd(&outF[rank], contrib);
}

// ---------------------------------------------------------------- launch
extern "C" void kernel_launch(void* const* d_in, const int* in_sizes, int n_in,
                              void* d_out, int out_size)
{
    const int4*  coords = (const int4*)d_in[0];
    const float* kern   = (const float*)d_in[1];
    float*       out    = (float*)d_out;
    int n = in_sizes[0] / 4;

    float* outF = out + 4ll * n;

    uint32_t initThreads = NWORDS / 4 + (uint32_t)n / 4 + NBLK;
    k0_init<<<(initThreads + TPB - 1) / TPB, TPB>>>(outF, (uint32_t)n);
    k1_build<<<(n + TPB - 1) / TPB, TPB>>>(coords, n);
    k2_sweep<<<NBLK, TPB>>>(out);
    k3_tail<<<256, TPB>>>(out, n);
    k4_feats<<<(n + TPB - 1) / TPB, TPB>>>(kern, outF, n);
}

// round 6
// speedup vs baseline: 1.0941x; 1.0941x over previous
#include <cuda_runtime.h>
#include <stdint.h>

// Key space: b in [0,256), px,py,pz in [0,128)  ->  2^29 keys -> 2^24 32-bit words
#define NWORDS    (1u << 24)
#define TPB       256
#define WPT       16                      // words per thread in the sweep
#define BLK_WORDS (TPB * WPT)             // 4096 words per block
#define NBLK      (NWORDS / BLK_WORDS)    // 4096 blocks
#define NSEG      (NWORDS / 8)            // 8-word (32B sector) segments
#define MAXN      4194304u
#define CAP       2048                    // staged keys per block (expect ~1000)

#define FLAG_AGG  (1u << 30)
#define FLAG_PRE  (2u << 30)
#define VAL_MASK  0x3FFFFFFFu

__device__ uint32_t g_bitmap[NWORDS];     // 64 MB presence bitmap
__device__ uint32_t g_segBase[NSEG];      //  8 MB absolute rank at each 8-word segment
__device__ uint32_t g_keys[MAXN];         // 16 MB packed (pos<<29)|key per point
__device__ uint32_t g_status[NBLK];       // decoupled-lookback status (flag|value)

// ---------------------------------------------------------------- K0: zero bitmap
__global__ __launch_bounds__(TPB) void k0_init()
{
    uint32_t i = blockIdx.x * TPB + threadIdx.x;
    ((uint4*)g_bitmap)[i] = make_uint4(0u, 0u, 0u, 0u);
}

// ---------------------------------------------------------------- K1: mark + pack + zero feats/status
__global__ __launch_bounds__(TPB) void k1_build(const int4* __restrict__ coords,
                                                float* __restrict__ outF, int n)
{
    int i = blockIdx.x * TPB + threadIdx.x;
    if (i < n) {
        int4 c = __ldcs(&coords[i]);
        uint32_t key = ((uint32_t)c.x << 21) | ((uint32_t)(c.y >> 1) << 14)
                     | ((uint32_t)(c.z >> 1) << 7) | (uint32_t)(c.w >> 1);
        uint32_t pos = (uint32_t)((c.y & 1) | ((c.z & 1) << 1) | ((c.w & 1) << 2));
        __stcs(&g_keys[i], (pos << 29) | key);
        atomicOr(&g_bitmap[key >> 5], 1u << (key & 31));
    }
    if (i < n / 4) ((float4*)outF)[i] = make_float4(0.f, 0.f, 0.f, 0.f);
    if (i < NBLK)  g_status[i] = 0u;
}

// ---------------------------------------------------------------- K2: fused sweep
// One bitmap pass: popcount + block scan, decoupled lookback, smem-staged
// coalesced coords emit, segment rank bases, and tail -1 fill (last block).
__global__ __launch_bounds__(TPB) void k2_sweep(float* __restrict__ out, int n)
{
    __shared__ uint32_t s_keys[CAP];
    __shared__ uint32_t s_warp[TPB / 32];
    __shared__ uint32_t s_excl, s_agg;
    uint32_t t    = threadIdx.x;
    uint32_t lane = t & 31, wid = t >> 5;
    uint32_t bid  = blockIdx.x;
    uint32_t base = bid * BLK_WORDS + t * WPT;

    uint32_t words[WPT];
    const uint4* p = (const uint4*)(g_bitmap + base);
    uint32_t tot = 0;
#pragma unroll
    for (int i = 0; i < 4; i++) {
        uint4 v = p[i];
        words[4 * i + 0] = v.x; words[4 * i + 1] = v.y;
        words[4 * i + 2] = v.z; words[4 * i + 3] = v.w;
    }
#pragma unroll
    for (int i = 0; i < WPT; i++) tot += __popc(words[i]);

    // warp inclusive scan
    uint32_t inc = tot;
#pragma unroll
    for (int o = 1; o < 32; o <<= 1) {
        uint32_t x = __shfl_up_sync(0xFFFFFFFFu, inc, o);
        if (lane >= o) inc += x;
    }
    if (lane == 31) s_warp[wid] = inc;
    __syncthreads();

    if (wid == 0) {
        uint32_t v = (lane < TPB / 32) ? s_warp[lane] : 0u;
        uint32_t vi = v;
#pragma unroll
        for (int o = 1; o < TPB / 32; o <<= 1) {
            uint32_t x = __shfl_up_sync(0xFFFFFFFFu, vi, o);
            if (lane >= o) vi += x;
        }
        if (lane < TPB / 32) s_warp[lane] = vi - v;    // exclusive warp prefix
        if (lane == TPB / 32 - 1) {
            s_agg = vi;                                 // block aggregate
            if (bid == 0) {
                atomicExch(&g_status[0], FLAG_PRE | vi);
                s_excl = 0u;
            } else {
                atomicExch(&g_status[bid], FLAG_AGG | vi);
            }
        }
    }
    __syncthreads();
    uint32_t threadExcl = s_warp[wid] + inc - tot;      // block-relative exclusive prefix

    // decoupled lookback (warp 0)
    if (bid != 0 && wid == 0) {
        uint32_t excl = 0;
        int pos = (int)bid - 1;
        while (pos >= 0) {
            int idx = pos - (int)lane;
            uint32_t sv;
            if (idx >= 0) {
                do { sv = *((volatile uint32_t*)&g_status[idx]); }
                while ((sv >> 30) == 0u);
            } else {
                sv = FLAG_PRE;
            }
            uint32_t flag = sv >> 30;
            uint32_t val  = sv & VAL_MASK;
            uint32_t ball = __ballot_sync(0xFFFFFFFFu, flag == 2u);
            if (ball) {
                int fp = __ffs(ball) - 1;
                uint32_t contrib = ((int)lane <= fp) ? val : 0u;
                excl += __reduce_add_sync(0xFFFFFFFFu, contrib);
                break;
            } else {
                excl += __reduce_add_sync(0xFFFFFFFFu, val);
                pos -= 32;
            }
        }
        if (lane == 0) s_excl = excl;
    }
    __syncthreads();
    uint32_t excl = s_excl, agg = s_agg;
    if (bid != 0 && t == 0)
        atomicExch(&g_status[bid], FLAG_PRE | ((excl + agg) & VAL_MASK));

    // stage keys at block-relative rank; write segment bases
    float4* outc = (float4*)out;
    {
        uint32_t running = excl + threadExcl;            // absolute rank
#pragma unroll
        for (int i = 0; i < WPT; i++) {
            uint32_t w = base + i;
            if ((i & 7) == 0) g_segBase[w >> 3] = running;
            uint32_t word = words[i];
            while (word) {
                int b = __ffs(word) - 1;
                word &= word - 1;
                uint32_t key = (w << 5) + (uint32_t)b;
                uint32_t local = running - excl;
                if (local < CAP) {
                    s_keys[local] = key;                 // common path
                } else {                                 // overflow fallback
                    __stcs(&outc[running],
                           make_float4((float)(key >> 21), (float)((key >> 14) & 127),
                                       (float)((key >> 7) & 127), (float)(key & 127)));
                }
                running++;
            }
        }
    }
    __syncthreads();

    // coalesced decode + store of staged keys
    uint32_t cnt = (agg < CAP) ? agg : CAP;
    for (uint32_t j = t; j < cnt; j += TPB) {
        uint32_t key = s_keys[j];
        __stcs(&outc[excl + j],
               make_float4((float)(key >> 21), (float)((key >> 14) & 127),
                           (float)((key >> 7) & 127), (float)(key & 127)));
    }

    // last block fills the -1 tail (it knows the grand total)
    if (bid == NBLK - 1) {
        uint32_t total = excl + agg;
        for (uint32_t i = total + t; i < (uint32_t)n; i += TPB)
            __stcs(&outc[i], make_float4(-1.f, -1.f, -1.f, -1.f));
    }
}

// ---------------------------------------------------------------- K3: scatter feats
__global__ __launch_bounds__(TPB) void k3_feats(const float* __restrict__ kern,
                                                float* __restrict__ outF, int n)
{
    int i = blockIdx.x * TPB + threadIdx.x;
    if (i >= n) return;
    uint32_t packed = __ldcs(&g_keys[i]);
    uint32_t pos = packed >> 29;
    uint32_t key = packed & ((1u << 29) - 1u);
    uint32_t w = key >> 5, bit = key & 31;
    uint32_t seg = w >> 3, j = w & 7;

    const uint4* sp = (const uint4*)(g_bitmap + (seg << 3));
    uint4 lo = __ldg(&sp[0]), hi = __ldg(&sp[1]);
    uint32_t sw[8] = { lo.x, lo.y, lo.z, lo.w, hi.x, hi.y, hi.z, hi.w };

    uint32_t rank = __ldg(&g_segBase[seg]);
#pragma unroll
    for (uint32_t k = 0; k < 8; k++)
        if (k < j) rank += __popc(sw[k]);
    rank += __popc(sw[j] & ((1u << bit) - 1u));

    float contrib = (float)(1u << pos) * __ldg(&kern[pos]);
    atomicAdd(&outF[rank], contrib);
}

// ---------------------------------------------------------------- launch
extern "C" void kernel_launch(void* const* d_in, const int* in_sizes, int n_in,
                              void* d_out, int out_size)
{
    const int4*  coords = (const int4*)d_in[0];
    const float* kern   = (const float*)d_in[1];
    float*       out    = (float*)d_out;
    int n = in_sizes[0] / 4;

    float* outF = out + 4ll * n;

    k0_init<<<(NWORDS / 4) / TPB, TPB>>>();
    k1_build<<<(n + TPB - 1) / TPB, TPB>>>(coords, outF, n);
    k2_sweep<<<NBLK, TPB>>>(out, n);
    k3_feats<<<(n + TPB - 1) / TPB, TPB>>>(kern, outF, n);
}